// round 9
// baseline (speedup 1.0000x reference)
#include <cuda_runtime.h>
#include <math.h>

#define BB 256
#define NN 1000
#define DD 256
#define HH 8
#define DHH 32
#define NEG (-1000000000.0f)

// Intermediates (device globals: no allocation allowed)
__device__ float g_q1[BB * DD];  // glimpse_q
__device__ float g_q2[BB * DD];  // head_in

// ---------------------------------------------------------------------------
// Phase 1 (tiled): step_context = concat(cur, graph_ctx, dyn) @ W_ctx
// grid = (16 batch-groups, 16 col-chunks), block = 512 (1 batch x 1 col each),
// dynamic smem ~99KB.
// ---------------------------------------------------------------------------
__global__ void ctx2_kernel(const float* __restrict__ node_emb,
                            const float* __restrict__ graph_ctx,
                            const float* __restrict__ cap,
                            const float* __restrict__ rd,
                            const float* __restrict__ rn,
                            const float* __restrict__ Wc,
                            const int* __restrict__ head) {
    extern __shared__ float sm[];
    float* Ws = sm;              // 515*32
    float* xs = sm + 515 * 32;   // 16*515
    int bg = blockIdx.x, cc = blockIdx.y;
    int t = threadIdx.x;
    int j0 = cc * 32, b0 = bg * 16;

    for (int idx = t; idx < 515 * 32; idx += 512) {
        int r = idx >> 5, c = idx & 31;
        Ws[idx] = Wc[r * 512 + j0 + c];
    }
    for (int idx = t; idx < 16 * 515; idx += 512) {
        int b = idx / 515, i = idx - b * 515;
        int bA = b0 + b;
        float v;
        if (i < 256) {
            int hd = head[bA];
            v = node_emb[((size_t)bA * NN + hd) * DD + i];
        } else if (i < 512) v = graph_ctx[bA * DD + (i - 256)];
        else v = (i == 512) ? cap[bA] : (i == 513) ? rd[bA] : rn[bA];
        xs[idx] = v;
    }
    __syncthreads();

    int c = t & 31, bp = t >> 5;   // bp in 0..15
    const float* xA = xs + bp * 515;
    float a0 = 0.f;
#pragma unroll 5
    for (int i = 0; i < 515; i++)
        a0 = fmaf(xA[i], Ws[i * 32 + c], a0);
    int j = j0 + c;
    int bA = b0 + bp;
    if (j < 256) g_q1[bA * DD + j] = a0;
    else         g_q2[bA * DD + j - 256] = a0;
}

// ---------------------------------------------------------------------------
// Mega kernel: per-batch fused feas + dual-query MHA (8 heads) + proj + logits
// grid = B, block = 1024, dynamic smem ~70.8 KB, 2 blocks/SM.
// ---------------------------------------------------------------------------
__global__ __launch_bounds__(1024, 2)
void mega_kernel(const float* __restrict__ K,
                 const float* __restrict__ V,
                 const float* __restrict__ LK,
                 const float* __restrict__ Wout,
                 const float* __restrict__ Wsa,
                 const int* __restrict__ feasible,
                 float* __restrict__ out_logp,
                 float* __restrict__ out_head) {
    extern __shared__ float sm[];
    float* s1    = sm;            // 8000
    float* s2    = sm + 8000;     // 8000
    float* q1s   = sm + 16000;    // 256
    float* q2s   = sm + 16256;    // 256
    float* att1s = sm + 16512;    // 256
    float* att2s = sm + 16768;    // 256
    float* gls   = sm + 17024;    // 256
    float* red1  = sm + 17280;    // 32
    float* red2  = sm + 17312;    // 32
    float* redz1 = sm + 17344;    // 32
    float* redz2 = sm + 17376;    // 32
    float* bc    = sm + 17408;    // 2 (+2 pad)
    int*   ired  = (int*)(sm + 17412);                  // 32 ints
    unsigned char* feas = (unsigned char*)(sm + 17444); // 1024 bytes
    // total = (17444 + 256) * 4 = 70800 bytes

    int b = blockIdx.x;
    int t = threadIdx.x;
    int warp = t >> 5, lane = t & 31;

    // ---- load queries ----
    if (t < DD) { q1s[t] = g_q1[b * DD + t]; q2s[t] = g_q2[b * DD + t]; }

    // ---- feasibility + no-feasible fix ----
    int f = 0;
    if (t < NN) { f = (feasible[b * NN + t] != 0); feas[t] = (unsigned char)f; }
    else feas[t] = 0;
    int any = __any_sync(0xffffffffu, f);
    if (lane == 0) ired[warp] = any;
    __syncthreads();
    if (t == 0) {
        int a = 0;
#pragma unroll
        for (int i = 0; i < 32; i++) a |= ired[i];
        if (!a) feas[0] = 1;
    }
    __syncthreads();

    // ---- scores: coalesced. Head h = warp>>2; warp covers 4 rows per LDG.128.
    // lane l: row = base + (l>>3), float4-chunk = l&7.
    int h = warp >> 2, w4 = warp & 3;
    int hh = t & 127;
    const float4* Kb = (const float4*)(K + (size_t)(b * HH + h) * NN * DHH);
    float4 qa = ((const float4*)(q1s + h * DHH))[lane & 7];
    float4 qb = ((const float4*)(q2s + h * DHH))[lane & 7];
    const float scale = 0.17677669529663687f; // 1/sqrt(32)
    float m1l = NEG, m2l = NEG;
    int rsub = lane >> 3;         // 0..3
    for (int i = 0; i < 63; i++) {
        int n = w4 * 4 + i * 16 + rsub;
        if (n < NN) {
            float4 kv = Kb[n * 8 + (lane & 7)];
            float d1 = fmaf(kv.x, qa.x, fmaf(kv.y, qa.y, fmaf(kv.z, qa.z, kv.w * qa.w)));
            float d2 = fmaf(kv.x, qb.x, fmaf(kv.y, qb.y, fmaf(kv.z, qb.z, kv.w * qb.w)));
            // reduce across the 8 lanes of this row
#pragma unroll
            for (int o = 4; o; o >>= 1) {
                d1 += __shfl_xor_sync(0xffffffffu, d1, o);
                d2 += __shfl_xor_sync(0xffffffffu, d2, o);
            }
            if ((lane & 7) == 0) {
                bool fe = feas[n] != 0;
                float v1 = fe ? d1 * scale : NEG;
                float v2 = fe ? d2 * scale : NEG;
                s1[h * NN + n] = v1; s2[h * NN + n] = v2;
                m1l = fmaxf(m1l, v1); m2l = fmaxf(m2l, v2);
            }
        } else {
            // keep shfl participation uniform
#pragma unroll
            for (int o = 4; o; o >>= 1) {
                (void)__shfl_xor_sync(0xffffffffu, 0.f, o);
                (void)__shfl_xor_sync(0xffffffffu, 0.f, o);
            }
        }
    }
#pragma unroll
    for (int o = 16; o; o >>= 1) {
        m1l = fmaxf(m1l, __shfl_xor_sync(0xffffffffu, m1l, o));
        m2l = fmaxf(m2l, __shfl_xor_sync(0xffffffffu, m2l, o));
    }
    if (lane == 0) { red1[warp] = m1l; red2[warp] = m2l; }
    __syncthreads();
    float m1 = fmaxf(fmaxf(red1[h * 4], red1[h * 4 + 1]), fmaxf(red1[h * 4 + 2], red1[h * 4 + 3]));
    float m2 = fmaxf(fmaxf(red2[h * 4], red2[h * 4 + 1]), fmaxf(red2[h * 4 + 2], red2[h * 4 + 3]));

    // ---- exp + per-head Z (128 threads per head, stride over NN) ----
    float z1l = 0.f, z2l = 0.f;
    for (int n = hh; n < NN; n += 128) {
        float p1 = expf(s1[h * NN + n] - m1);
        float p2 = expf(s2[h * NN + n] - m2);
        s1[h * NN + n] = p1; s2[h * NN + n] = p2;
        z1l += p1; z2l += p2;
    }
#pragma unroll
    for (int o = 16; o; o >>= 1) {
        z1l += __shfl_xor_sync(0xffffffffu, z1l, o);
        z2l += __shfl_xor_sync(0xffffffffu, z2l, o);
    }
    if (lane == 0) { redz1[warp] = z1l; redz2[warp] = z2l; }
    __syncthreads();

    // ---- V pass: 4 warps per head, lane = d (coalesced 128B rows) ----
    const float* Vb = V + (size_t)(b * HH + h) * NN * DHH;
    float a1 = 0.f, a2 = 0.f;
#pragma unroll 5
    for (int n = w4; n < NN; n += 4) {
        float v = Vb[n * DHH + lane];
        a1 = fmaf(s1[h * NN + n], v, a1);
        a2 = fmaf(s2[h * NN + n], v, a2);
    }
    __syncthreads();          // all warps done reading exp(s) from s1/s2
    s1[t] = a1;               // reuse: V partials
    s2[t] = a2;
    __syncthreads();
    if (t < 512) {
        int q = t >> 8, idx = t & 255;
        int h2 = idx >> 5, d = idx & 31;
        const float* sr = q ? s2 : s1;
        float sum = sr[h2 * 128 + d] + sr[h2 * 128 + 32 + d]
                  + sr[h2 * 128 + 64 + d] + sr[h2 * 128 + 96 + d];
        const float* rz = q ? redz2 : redz1;
        float Z = rz[h2 * 4] + rz[h2 * 4 + 1] + rz[h2 * 4 + 2] + rz[h2 * 4 + 3];
        if (q == 0) att1s[idx] = sum / Z;
        else        att2s[idx] = sum / Z;
    }
    __syncthreads();

    // ---- proj: glimpse = att1 @ Wout; head_enc = att2 @ Wsa ----
    {
        int half = t >> 8;  // 0..3
        int j = t & 255;
        float acc = 0.f;
        if (half < 2) {
            int i0 = half * 128;
            const float* wp = Wout + (size_t)i0 * DD + j;
#pragma unroll 8
            for (int i = 0; i < 128; i++) acc = fmaf(att1s[i0 + i], wp[i * DD], acc);
        } else {
            int i0 = (half - 2) * 128;
            const float* wp = Wsa + (size_t)i0 * DD + j;
#pragma unroll 8
            for (int i = 0; i < 128; i++) acc = fmaf(att2s[i0 + i], wp[i * DD], acc);
        }
        __syncthreads();
        s1[t] = acc;          // reuse: proj partials
        __syncthreads();
        if (t < 256) gls[t] = s1[t] + s1[256 + t];
        else if (t < 512) out_head[b * DD + (t - 256)] = s1[512 + (t - 256)] + s1[768 + (t - 256)];
    }
    __syncthreads();

    // ---- logits: coalesced. Warp covers 2 rows/iter; lane l: row = l>>4,
    // 16 lanes sweep the 1KB row in 4 LDG.128. ----
    int rhalf = lane >> 4;        // 0 or 1
    int csel = lane & 15;         // float4 chunk within group
    const float4* gv = (const float4*)gls;
    for (int k = 0; k < 16; k++) {
        int n = warp * 2 + k * 64 + rhalf;
        float d = 0.f;
        if (n < NN) {
            const float4* r = (const float4*)(LK + ((size_t)b * NN + n) * DD);
#pragma unroll
            for (int jj = 0; jj < 4; jj++) {
                float4 kv = r[csel + jj * 16];
                float4 g = gv[csel + jj * 16];
                d = fmaf(kv.x, g.x, d); d = fmaf(kv.y, g.y, d);
                d = fmaf(kv.z, g.z, d); d = fmaf(kv.w, g.w, d);
            }
        }
#pragma unroll
        for (int o = 8; o; o >>= 1) d += __shfl_xor_sync(0xffffffffu, d, o);
        if (csel == 0 && n < NN) {
            float lg = 10.0f * tanhf(d * 0.0625f);
            s1[n] = feas[n] ? lg : NEG;   // reuse s1: logits buffer
        }
    }
    __syncthreads();

    // ---- log-softmax over s1[0..999] ----
    float l = (t < NN) ? s1[t] : NEG;
    float v = l;
#pragma unroll
    for (int o = 16; o; o >>= 1) v = fmaxf(v, __shfl_xor_sync(0xffffffffu, v, o));
    if (lane == 0) red1[warp] = v;
    __syncthreads();
    if (t < 32) {
        float x = red1[t];
#pragma unroll
        for (int o = 16; o; o >>= 1) x = fmaxf(x, __shfl_xor_sync(0xffffffffu, x, o));
        if (t == 0) bc[0] = x;
    }
    __syncthreads();
    float m = bc[0];
    float e = (t < NN) ? expf(l - m) : 0.f;
#pragma unroll
    for (int o = 16; o; o >>= 1) e += __shfl_xor_sync(0xffffffffu, e, o);
    if (lane == 0) red2[warp] = e;
    __syncthreads();
    if (t < 32) {
        float x = red2[t];
#pragma unroll
        for (int o = 16; o; o >>= 1) x += __shfl_xor_sync(0xffffffffu, x, o);
        if (t == 0) bc[1] = x;
    }
    __syncthreads();
    float lse = m + logf(bc[1]);
    if (t < NN) out_logp[b * NN + t] = l - lse;
}

// ---------------------------------------------------------------------------
extern "C" void kernel_launch(void* const* d_in, const int* in_sizes, int n_in,
                              void* d_out, int out_size) {
    const float* node_emb  = (const float*)d_in[0];
    const float* graph_ctx = (const float*)d_in[1];
    const float* K         = (const float*)d_in[2];
    const float* V         = (const float*)d_in[3];
    const float* LK        = (const float*)d_in[4];
    const float* cap       = (const float*)d_in[5];
    const float* rd        = (const float*)d_in[6];
    const float* rn        = (const float*)d_in[7];
    const float* Wc        = (const float*)d_in[8];
    const float* Wout      = (const float*)d_in[9];
    const float* Wsa       = (const float*)d_in[10];
    const int*   head      = (const int*)d_in[11];
    const int*   feasible  = (const int*)d_in[12];
    float* out = (float*)d_out;

    static bool attr_done = false;
    if (!attr_done) {
        cudaFuncSetAttribute(ctx2_kernel, cudaFuncAttributeMaxDynamicSharedMemorySize, 98880);
        cudaFuncSetAttribute(mega_kernel, cudaFuncAttributeMaxDynamicSharedMemorySize, 70912);
        attr_done = true;
    }

    ctx2_kernel<<<dim3(16, 16), 512, 98880>>>(node_emb, graph_ctx, cap, rd, rn, Wc, head);
    mega_kernel<<<BB, 1024, 70800>>>(K, V, LK, Wout, Wsa, feasible, out, out + BB * NN);
}